// round 12
// baseline (speedup 1.0000x reference)
#include <cuda_runtime.h>
#include <cuda_fp16.h>
#include <cstdint>
#include <math.h>

#define THREADS 384
constexpr float LN_EPS = 1e-5f, SCALE = 0.17677669529663687f;

constexpr int AST = 208;   // activation tile row stride bytes (104 halves)
constexpr int WST = 208;   // qkv/proj/fc1 W tile stride bytes (16B-aligned)
constexpr int HST = 400;   // hid & fc2-W stride bytes

constexpr int OF_RPB = 0, OF_BIAS = 2704, OF_LNP = 5392, OF_RIDX = 6928;
constexpr int OF_WQKV = 11024;   // 288 x 208 = 59904
constexpr int OF_WPRJ = 70928;   // 96 x 208  = 19968
constexpr int OF_WFC1 = 90896;   // 192 x 208 = 39936
constexpr int OF_WFC2 = 130832;  // 96 x 400  = 38400
constexpr int OF_A  = 169232;    // 64x208B: ln1 -> attn-out -> ln2
constexpr int OF_Q  = 182544;    // q -> proj-out(f16)
constexpr int OF_K  = 195856;    // k
constexpr int OF_V  = 209168;    // v (row-major)
constexpr int OF_HID = OF_K;     // 64 x 400 (overlays K+V)
constexpr int SMEM_TOTAL = 222480;
constexpr int NWIN = 8192;

__device__ __forceinline__ uint32_t smem_u32(const void* p) {
  uint32_t a; asm("{ .reg .u64 t; cvta.to.shared.u64 t, %1; cvt.u32.u64 %0, t; }" : "=r"(a) : "l"(p)); return a;
}
__device__ __forceinline__ uint32_t pkh(float lo, float hi) {
  __half2 h = __floats2half2_rn(lo, hi);
  return *reinterpret_cast<uint32_t*>(&h);
}
__device__ __forceinline__ void ldm4(uint32_t* r, uint32_t a) {
  asm volatile("ldmatrix.sync.aligned.m8n8.x4.shared.b16 {%0,%1,%2,%3}, [%4];"
               : "=r"(r[0]), "=r"(r[1]), "=r"(r[2]), "=r"(r[3]) : "r"(a));
}
__device__ __forceinline__ void ldm2(uint32_t* r, uint32_t a) {
  asm volatile("ldmatrix.sync.aligned.m8n8.x2.shared.b16 {%0,%1}, [%2];"
               : "=r"(r[0]), "=r"(r[1]) : "r"(a));
}
__device__ __forceinline__ void ldm2t(uint32_t* r, uint32_t a) {
  asm volatile("ldmatrix.sync.aligned.m8n8.x2.trans.shared.b16 {%0,%1}, [%2];"
               : "=r"(r[0]), "=r"(r[1]) : "r"(a));
}
__device__ __forceinline__ void mma16816(float* d, const uint32_t* a, const uint32_t* b) {
  asm volatile(
      "mma.sync.aligned.m16n8k16.row.col.f32.f16.f16.f32 "
      "{%0,%1,%2,%3}, {%4,%5,%6,%7}, {%8,%9}, {%0,%1,%2,%3};"
      : "+f"(d[0]), "+f"(d[1]), "+f"(d[2]), "+f"(d[3])
      : "r"(a[0]), "r"(a[1]), "r"(a[2]), "r"(a[3]), "r"(b[0]), "r"(b[1]));
}

template <int NT, int KS>
__device__ __forceinline__ void wgemm(uint32_t aB, int aStr, uint32_t wB, int wStr,
                                      int m0, int lane, float (*d)[4]) {
#pragma unroll
  for (int j = 0; j < NT; ++j) { d[j][0] = d[j][1] = d[j][2] = d[j][3] = 0.f; }
  const uint32_t aRow = aB + (uint32_t)((m0 + (lane & 7) + ((lane >> 3) & 1) * 8) * aStr + (lane >> 4) * 16);
  const uint32_t wRow = wB + (uint32_t)((lane & 7) * wStr + ((lane >> 3) & 1) * 16);
#pragma unroll
  for (int s = 0; s < KS; ++s) {
    uint32_t a[4];
    ldm4(a, aRow + 32 * s);
#pragma unroll
    for (int j = 0; j < NT; ++j) {
      uint32_t b[2];
      ldm2(b, wRow + (uint32_t)(8 * j * wStr) + 32 * s);
      mma16816(d[j], a, b);
    }
  }
}

template <int ROWS, int K, int WSTR>
__device__ __forceinline__ void load_w(char* SM, int off, const float* __restrict__ w) {
  for (int p = threadIdx.x; p < ROWS * K / 2; p += THREADS) {
    int row = (2 * p) / K, col = (2 * p) % K;
    float2 v = *(const float2*)&w[row * K + col];
    *(uint32_t*)(SM + off + row * WSTR + col * 2) = pkh(v.x, v.y);
  }
}

__global__ void __launch_bounds__(THREADS, 1)
swin_kernel(const float* __restrict__ x,
            const float* __restrict__ qkv_w, const float* __restrict__ qkv_b,
            const float* __restrict__ proj_w, const float* __restrict__ proj_b,
            const float* __restrict__ rpb,
            const float* __restrict__ n1g, const float* __restrict__ n1b,
            const float* __restrict__ n2g, const float* __restrict__ n2b,
            const float* __restrict__ fc1_w, const float* __restrict__ fc1_b,
            const float* __restrict__ fc2_w, const float* __restrict__ fc2_b,
            float* __restrict__ out) {
  extern __shared__ char SM[];
  const uint32_t sb = smem_u32(SM);
  const int tid = threadIdx.x, lane = tid & 31, warp = tid >> 5;
  const int slab = warp & 3, cg = warp >> 2;         // 4 row-slabs x 3 col-groups
  const int m0 = slab * 16, qr = lane >> 2, qc = lane & 3;
  const int row = tid >> 2, rq = tid & 3;            // LN mapping (tid<256)

  float* rpbs = (float*)(SM + OF_RPB);
  float* bias = (float*)(SM + OF_BIAS);
  float* lnp  = (float*)(SM + OF_LNP);
  uint8_t* RIDX = (uint8_t*)(SM + OF_RIDX);
  for (int i = tid; i < 675; i += THREADS) rpbs[i] = rpb[i];
  for (int i = tid; i < 288; i += THREADS) bias[i] = qkv_b[i];
  for (int i = tid; i < 96; i += THREADS)  bias[288 + i] = proj_b[i];
  for (int i = tid; i < 192; i += THREADS) bias[384 + i] = fc1_b[i];
  for (int i = tid; i < 96; i += THREADS)  bias[576 + i] = fc2_b[i];
  for (int i = tid; i < 96; i += THREADS) {
    lnp[i] = n1g[i]; lnp[96 + i] = n1b[i]; lnp[192 + i] = n2g[i]; lnp[288 + i] = n2b[i];
  }
  for (int i = tid; i < 4096; i += THREADS) {
    int n = i >> 6, m = i & 63;
    RIDX[i] = (uint8_t)(((n >> 3) - (m >> 3) + 7) * 15 + ((n & 7) - (m & 7) + 7));
  }
  load_w<288, 96, WST>(SM, OF_WQKV, qkv_w);
  load_w<96, 96, WST>(SM, OF_WPRJ, proj_w);
  load_w<192, 96, WST>(SM, OF_WFC1, fc1_w);
  load_w<96, 192, HST>(SM, OF_WFC2, fc2_w);
  __syncthreads();

  // LN1 for window wi -> A tile (threads 0..255, 4 per row)
  auto ln1 = [&](int wi) {
    if (tid >= 256) return;
    const int wb = wi >> 10, wh = (wi >> 5) & 31, ww = wi & 31;
    const float* xp = x + ((size_t)wb * 96) * 65536 +
                      (size_t)(wh * 8 + (row >> 3)) * 256 + ww * 8 + (row & 7);
    float v[24], s = 0.f, s2 = 0.f;
#pragma unroll
    for (int k = 0; k < 24; ++k) {
      float u = xp[(size_t)(24 * rq + k) * 65536];
      v[k] = u; s += u; s2 += u * u;
    }
    s  += __shfl_xor_sync(0xffffffffu, s, 1);  s  += __shfl_xor_sync(0xffffffffu, s, 2);
    s2 += __shfl_xor_sync(0xffffffffu, s2, 1); s2 += __shfl_xor_sync(0xffffffffu, s2, 2);
    float mu = s * (1.f / 96.f);
    float rs = rsqrtf(s2 * (1.f / 96.f) - mu * mu + LN_EPS);
#pragma unroll
    for (int k = 0; k < 12; ++k) {
      int c = 24 * rq + 2 * k;
      float a = (v[2 * k] - mu) * rs * lnp[c] + lnp[96 + c];
      float b = (v[2 * k + 1] - mu) * rs * lnp[c + 1] + lnp[96 + c + 1];
      *(uint32_t*)(SM + OF_A + row * AST + 2 * c) = pkh(a, b);
    }
  };

  int w = blockIdx.x;
  if (w < NWIN) ln1(w);

  for (; w < NWIN; w += gridDim.x) {
    __syncthreads();  // LN1(w) visible

    // ---- QKV: warp (slab, cg) does 32 cols of each of q,k,v ----
#pragma unroll
    for (int c = 0; c < 3; ++c) {
      float d[4][4];
      wgemm<4, 6>(sb + OF_A, AST, sb + OF_WQKV + (96 * c + 32 * cg) * WST, WST, m0, lane, d);
      const int dst = (c == 0) ? OF_Q : (c == 1 ? OF_K : OF_V);
      const float sc = (c == 0) ? SCALE : 1.f;
#pragma unroll
      for (int j = 0; j < 4; ++j) {
        int col = 32 * cg + 8 * j + 2 * qc;
        float b0 = bias[96 * c + col], b1 = bias[96 * c + col + 1];
        *(uint32_t*)(SM + dst + (m0 + qr) * AST + col * 2)     = pkh((d[j][0] + b0) * sc, (d[j][1] + b1) * sc);
        *(uint32_t*)(SM + dst + (m0 + qr + 8) * AST + col * 2) = pkh((d[j][2] + b0) * sc, (d[j][3] + b1) * sc);
      }
    }
    __syncthreads();

    // ---- attention: warp = (slab, head=cg) ----
    {
      const int h = cg;
      const int nn0 = m0 + qr, nn1 = nn0 + 8;
      float ds[8][4];
#pragma unroll
      for (int j = 0; j < 8; ++j) { ds[j][0] = ds[j][1] = ds[j][2] = ds[j][3] = 0.f; }
#pragma unroll
      for (int s = 0; s < 2; ++s) {
        uint32_t a[4];
        ldm4(a, sb + OF_Q + (uint32_t)((m0 + (lane & 7) + ((lane >> 3) & 1) * 8) * AST + (h * 32 + s * 16 + (lane >> 4) * 8) * 2));
#pragma unroll
        for (int j = 0; j < 8; ++j) {
          uint32_t b[2];
          ldm2(b, sb + OF_K + (uint32_t)((8 * j + (lane & 7)) * AST + (h * 32 + s * 16 + ((lane >> 3) & 1) * 8) * 2));
          mma16816(ds[j], a, b);
        }
      }
      float mx0 = -1e30f, mx1 = -1e30f;
#pragma unroll
      for (int j = 0; j < 8; ++j) {
        int mmc = 8 * j + 2 * qc;
        ds[j][0] += rpbs[RIDX[nn0 * 64 + mmc] * 3 + h];
        ds[j][1] += rpbs[RIDX[nn0 * 64 + mmc + 1] * 3 + h];
        ds[j][2] += rpbs[RIDX[nn1 * 64 + mmc] * 3 + h];
        ds[j][3] += rpbs[RIDX[nn1 * 64 + mmc + 1] * 3 + h];
        mx0 = fmaxf(mx0, fmaxf(ds[j][0], ds[j][1]));
        mx1 = fmaxf(mx1, fmaxf(ds[j][2], ds[j][3]));
      }
      mx0 = fmaxf(mx0, __shfl_xor_sync(0xffffffffu, mx0, 1));
      mx0 = fmaxf(mx0, __shfl_xor_sync(0xffffffffu, mx0, 2));
      mx1 = fmaxf(mx1, __shfl_xor_sync(0xffffffffu, mx1, 1));
      mx1 = fmaxf(mx1, __shfl_xor_sync(0xffffffffu, mx1, 2));
      float s0 = 0.f, s1 = 0.f;
#pragma unroll
      for (int j = 0; j < 8; ++j) {
        ds[j][0] = __expf(ds[j][0] - mx0); ds[j][1] = __expf(ds[j][1] - mx0);
        ds[j][2] = __expf(ds[j][2] - mx1); ds[j][3] = __expf(ds[j][3] - mx1);
        s0 += ds[j][0] + ds[j][1]; s1 += ds[j][2] + ds[j][3];
      }
      s0 += __shfl_xor_sync(0xffffffffu, s0, 1); s0 += __shfl_xor_sync(0xffffffffu, s0, 2);
      s1 += __shfl_xor_sync(0xffffffffu, s1, 1); s1 += __shfl_xor_sync(0xffffffffu, s1, 2);
      float i0 = 1.f / s0, i1 = 1.f / s1;
      uint32_t pa[4][4];
#pragma unroll
      for (int kk = 0; kk < 4; ++kk) {
        pa[kk][0] = pkh(ds[2 * kk][0] * i0, ds[2 * kk][1] * i0);
        pa[kk][1] = pkh(ds[2 * kk][2] * i1, ds[2 * kk][3] * i1);
        pa[kk][2] = pkh(ds[2 * kk + 1][0] * i0, ds[2 * kk + 1][1] * i0);
        pa[kk][3] = pkh(ds[2 * kk + 1][2] * i1, ds[2 * kk + 1][3] * i1);
      }
      float o[4][4];
#pragma unroll
      for (int j = 0; j < 4; ++j) { o[j][0] = o[j][1] = o[j][2] = o[j][3] = 0.f; }
#pragma unroll
      for (int kk = 0; kk < 4; ++kk)
#pragma unroll
        for (int j = 0; j < 4; ++j) {
          uint32_t b[2];
          ldm2t(b, sb + OF_V + (uint32_t)((16 * kk + (lane & 15)) * AST + (h * 32 + 8 * j) * 2));
          mma16816(o[j], pa[kk], b);
        }
#pragma unroll
      for (int j = 0; j < 4; ++j) {
        int col = h * 32 + 8 * j + 2 * qc;
        *(uint32_t*)(SM + OF_A + (m0 + qr) * AST + col * 2)     = pkh(o[j][0], o[j][1]);
        *(uint32_t*)(SM + OF_A + (m0 + qr + 8) * AST + col * 2) = pkh(o[j][2], o[j][3]);
      }
    }
    __syncthreads();

    // ---- proj -> Q (f16) ----
    {
      float d[4][4];
      wgemm<4, 6>(sb + OF_A, AST, sb + OF_WPRJ + 32 * cg * WST, WST, m0, lane, d);
#pragma unroll
      for (int j = 0; j < 4; ++j) {
        int col = 32 * cg + 8 * j + 2 * qc;
        float b0 = bias[288 + col], b1 = bias[288 + col + 1];
        *(uint32_t*)(SM + OF_Q + (m0 + qr) * AST + col * 2)     = pkh(d[j][0] + b0, d[j][1] + b1);
        *(uint32_t*)(SM + OF_Q + (m0 + qr + 8) * AST + col * 2) = pkh(d[j][2] + b0, d[j][3] + b1);
      }
    }
    __syncthreads();

    // ---- LN2: Q -> A (f16) ----
    if (tid < 256) {
      const __half2* qrow = (const __half2*)(SM + OF_Q + row * AST);
      float v[24], s = 0.f, s2 = 0.f;
#pragma unroll
      for (int k = 0; k < 12; ++k) {
        float2 u = __half22float2(qrow[12 * rq + k]);
        v[2 * k] = u.x; v[2 * k + 1] = u.y;
        s += u.x + u.y; s2 += u.x * u.x + u.y * u.y;
      }
      s  += __shfl_xor_sync(0xffffffffu, s, 1);  s  += __shfl_xor_sync(0xffffffffu, s, 2);
      s2 += __shfl_xor_sync(0xffffffffu, s2, 1); s2 += __shfl_xor_sync(0xffffffffu, s2, 2);
      float mu = s * (1.f / 96.f);
      float rs = rsqrtf(s2 * (1.f / 96.f) - mu * mu + LN_EPS);
#pragma unroll
      for (int k = 0; k < 12; ++k) {
        int c = 24 * rq + 2 * k;
        float a = (v[2 * k] - mu) * rs * lnp[192 + c] + lnp[288 + c];
        float b = (v[2 * k + 1] - mu) * rs * lnp[192 + c + 1] + lnp[288 + c + 1];
        *(uint32_t*)(SM + OF_A + row * AST + 2 * c) = pkh(a, b);
      }
    }
    __syncthreads();

    // ---- fc1 + exact GELU -> hid (64 cols per cg) ----
    {
      float d[8][4];
      wgemm<8, 6>(sb + OF_A, AST, sb + OF_WFC1 + 64 * cg * WST, WST, m0, lane, d);
#pragma unroll
      for (int j = 0; j < 8; ++j) {
        int col = 64 * cg + 8 * j + 2 * qc;
        float b0 = bias[384 + col], b1 = bias[384 + col + 1];
        float u0 = d[j][0] + b0, u1 = d[j][1] + b1, u2 = d[j][2] + b0, u3 = d[j][3] + b1;
        u0 = 0.5f * u0 * (1.f + erff(u0 * 0.70710678118654752f));
        u1 = 0.5f * u1 * (1.f + erff(u1 * 0.70710678118654752f));
        u2 = 0.5f * u2 * (1.f + erff(u2 * 0.70710678118654752f));
        u3 = 0.5f * u3 * (1.f + erff(u3 * 0.70710678118654752f));
        *(uint32_t*)(SM + OF_HID + (m0 + qr) * HST + col * 2)     = pkh(u0, u1);
        *(uint32_t*)(SM + OF_HID + (m0 + qr + 8) * HST + col * 2) = pkh(u2, u3);
      }
    }
    __syncthreads();

    // ---- fc2 -> gmem with fused residual ; then LN1 of next window ----
    {
      float d[4][4];
      wgemm<4, 12>(sb + OF_HID, HST, sb + OF_WFC2 + 32 * cg * HST, HST, m0, lane, d);
      const int wb = w >> 10, wh = (w >> 5) & 31, ww = w & 31;
      const size_t base = ((size_t)wb * 96) * 65536 + (size_t)(wh * 8) * 256 + ww * 8;
      const int sp0 = (m0 >> 3) * 256 + qr, sp1 = sp0 + 256;
#pragma unroll
      for (int j = 0; j < 4; ++j) {
        int col = 32 * cg + 8 * j + 2 * qc;
        float b0 = bias[576 + col], b1 = bias[576 + col + 1];
        size_t o00 = base + (size_t)col * 65536 + sp0;
        size_t o10 = base + (size_t)col * 65536 + sp1;
        out[o00]         = d[j][0] + b0 + x[o00];
        out[o00 + 65536] = d[j][1] + b1 + x[o00 + 65536];
        out[o10]         = d[j][2] + b0 + x[o10];
        out[o10 + 65536] = d[j][3] + b1 + x[o10 + 65536];
      }
    }
    int wn = w + gridDim.x;
    if (wn < NWIN) ln1(wn);
  }
}

extern "C" void kernel_launch(void* const* d_in, const int* in_sizes, int n_in,
                              void* d_out, int out_size) {
  (void)in_sizes; (void)n_in; (void)out_size;
  int dev = 0, sms = 148;
  cudaGetDevice(&dev);
  cudaDeviceGetAttribute(&sms, cudaDevAttrMultiProcessorCount, dev);
  cudaFuncSetAttribute(swin_kernel, cudaFuncAttributeMaxDynamicSharedMemorySize, SMEM_TOTAL);
  swin_kernel<<<sms, THREADS, SMEM_TOTAL>>>(
      (const float*)d_in[0],
      (const float*)d_in[1], (const float*)d_in[2],
      (const float*)d_in[3], (const float*)d_in[4],
      (const float*)d_in[5],
      (const float*)d_in[6], (const float*)d_in[7],
      (const float*)d_in[8], (const float*)d_in[9],
      (const float*)d_in[10], (const float*)d_in[11],
      (const float*)d_in[12], (const float*)d_in[13],
      (float*)d_out);
}

// round 13
// speedup vs baseline: 1.4061x; 1.4061x over previous
#include <cuda_runtime.h>
#include <cuda_fp16.h>
#include <cstdint>
#include <math.h>

#define THREADS 256
constexpr float LN_EPS = 1e-5f, SCALE = 0.17677669529663687f;

constexpr int AST = 208;   // activation tile row stride bytes
constexpr int WST = 208;   // qkv/proj/fc1 W tile stride bytes
constexpr int HST = 400;   // hid & fc2-W stride bytes

constexpr int OF_RPB = 0, OF_BIAS = 2704, OF_LNP = 5392, OF_RIDX = 6928;
constexpr int OF_WQKV = 11024;   // 288 x 208
constexpr int OF_WPRJ = 70928;   // 96 x 208
constexpr int OF_WFC1 = 90896;   // 192 x 208
constexpr int OF_WFC2 = 130832;  // 96 x 400
constexpr int OF_A  = 169232;    // 64x208B
constexpr int OF_Q  = 182544;
constexpr int OF_K  = 195856;
constexpr int OF_V  = 209168;
constexpr int OF_HID = OF_K;     // 64 x 400 (overlays K+V)
constexpr int SMEM_TOTAL = 222480;
constexpr int NWIN = 8192;

__device__ __forceinline__ uint32_t smem_u32(const void* p) {
  uint32_t a; asm("{ .reg .u64 t; cvta.to.shared.u64 t, %1; cvt.u32.u64 %0, t; }" : "=r"(a) : "l"(p)); return a;
}
__device__ __forceinline__ uint32_t pkh(float lo, float hi) {
  __half2 h = __floats2half2_rn(lo, hi);
  return *reinterpret_cast<uint32_t*>(&h);
}
__device__ __forceinline__ void ldm4(uint32_t* r, uint32_t a) {
  asm volatile("ldmatrix.sync.aligned.m8n8.x4.shared.b16 {%0,%1,%2,%3}, [%4];"
               : "=r"(r[0]), "=r"(r[1]), "=r"(r[2]), "=r"(r[3]) : "r"(a));
}
__device__ __forceinline__ void ldm4t(uint32_t* r, uint32_t a) {
  asm volatile("ldmatrix.sync.aligned.m8n8.x4.trans.shared.b16 {%0,%1,%2,%3}, [%4];"
               : "=r"(r[0]), "=r"(r[1]), "=r"(r[2]), "=r"(r[3]) : "r"(a));
}
__device__ __forceinline__ void mma16816(float* d, const uint32_t* a, const uint32_t* b) {
  asm volatile(
      "mma.sync.aligned.m16n8k16.row.col.f32.f16.f16.f32 "
      "{%0,%1,%2,%3}, {%4,%5,%6,%7}, {%8,%9}, {%0,%1,%2,%3};"
      : "+f"(d[0]), "+f"(d[1]), "+f"(d[2]), "+f"(d[3])
      : "r"(a[0]), "r"(a[1]), "r"(a[2]), "r"(a[3]), "r"(b[0]), "r"(b[1]));
}

// paired-row base for x4 B loads: lanes 16-31 take the +8-row sibling tile
__device__ __forceinline__ uint32_t prow(uint32_t base, int stride, int lane) {
  return base + (uint32_t)((lane & 7) * stride + (lane >> 4) * 8 * stride + ((lane >> 3) & 1) * 16);
}

// C[16 x NT*8] = A[16 x 16*KS] @ W[NT*8 x 16*KS]^T per warp, NT even, paired-B x4 loads
template <int NT, int KS>
__device__ __forceinline__ void wgemm(uint32_t aB, int aStr, uint32_t wB, int wStr,
                                      int m0, int lane, float (*d)[4]) {
#pragma unroll
  for (int j = 0; j < NT; ++j) { d[j][0] = d[j][1] = d[j][2] = d[j][3] = 0.f; }
  const uint32_t aRow = aB + (uint32_t)((m0 + (lane & 7) + ((lane >> 3) & 1) * 8) * aStr + (lane >> 4) * 16);
  const uint32_t wRow = prow(wB, wStr, lane);
#pragma unroll
  for (int s = 0; s < KS; ++s) {
    uint32_t a[4];
    ldm4(a, aRow + 32 * s);
#pragma unroll
    for (int jp = 0; jp < NT / 2; ++jp) {
      uint32_t b[4];
      ldm4(b, wRow + (uint32_t)(16 * jp * wStr) + 32 * s);
      mma16816(d[2 * jp], a, b);
      mma16816(d[2 * jp + 1], a, b + 2);
    }
  }
}

template <int ROWS, int K, int WSTR>
__device__ __forceinline__ void load_w(char* SM, int off, const float* __restrict__ w) {
  for (int p = threadIdx.x; p < ROWS * K / 2; p += THREADS) {
    int row = (2 * p) / K, col = (2 * p) % K;
    float2 v = *(const float2*)&w[row * K + col];
    *(uint32_t*)(SM + off + row * WSTR + col * 2) = pkh(v.x, v.y);
  }
}

__global__ void __launch_bounds__(THREADS, 1)
swin_kernel(const float* __restrict__ x,
            const float* __restrict__ qkv_w, const float* __restrict__ qkv_b,
            const float* __restrict__ proj_w, const float* __restrict__ proj_b,
            const float* __restrict__ rpb,
            const float* __restrict__ n1g, const float* __restrict__ n1b,
            const float* __restrict__ n2g, const float* __restrict__ n2b,
            const float* __restrict__ fc1_w, const float* __restrict__ fc1_b,
            const float* __restrict__ fc2_w, const float* __restrict__ fc2_b,
            float* __restrict__ out) {
  extern __shared__ char SM[];
  const uint32_t sb = smem_u32(SM);
  const int tid = threadIdx.x, lane = tid & 31, warp = tid >> 5;
  const int slab = warp >> 1, g = warp & 1;
  const int m0 = slab * 16, qr = lane >> 2, qc = lane & 3;
  const int row = tid >> 2, rq = tid & 3;

  float* rpbs = (float*)(SM + OF_RPB);
  float* bias = (float*)(SM + OF_BIAS);
  float* lnp  = (float*)(SM + OF_LNP);
  uint8_t* RIDX = (uint8_t*)(SM + OF_RIDX);
  for (int i = tid; i < 675; i += THREADS) rpbs[i] = rpb[i];
  for (int i = tid; i < 288; i += THREADS) bias[i] = qkv_b[i];
  for (int i = tid; i < 96; i += THREADS)  bias[288 + i] = proj_b[i];
  for (int i = tid; i < 192; i += THREADS) bias[384 + i] = fc1_b[i];
  for (int i = tid; i < 96; i += THREADS)  bias[576 + i] = fc2_b[i];
  for (int i = tid; i < 96; i += THREADS) {
    lnp[i] = n1g[i]; lnp[96 + i] = n1b[i]; lnp[192 + i] = n2g[i]; lnp[288 + i] = n2b[i];
  }
  for (int i = tid; i < 4096; i += THREADS) {
    int n = i >> 6, m = i & 63;
    RIDX[i] = (uint8_t)(((n >> 3) - (m >> 3) + 7) * 15 + ((n & 7) - (m & 7) + 7));
  }
  load_w<288, 96, WST>(SM, OF_WQKV, qkv_w);
  load_w<96, 96, WST>(SM, OF_WPRJ, proj_w);
  load_w<192, 96, WST>(SM, OF_WFC1, fc1_w);
  load_w<96, 192, HST>(SM, OF_WFC2, fc2_w);
  __syncthreads();

  auto ln1 = [&](int wi) {
    const int wb = wi >> 10, wh = (wi >> 5) & 31, ww = wi & 31;
    const float* xp = x + ((size_t)wb * 96) * 65536 +
                      (size_t)(wh * 8 + (row >> 3)) * 256 + ww * 8 + (row & 7);
    float v[24], s = 0.f, s2 = 0.f;
#pragma unroll
    for (int k = 0; k < 24; ++k) {
      float u = xp[(size_t)(24 * rq + k) * 65536];
      v[k] = u; s += u; s2 += u * u;
    }
    s  += __shfl_xor_sync(0xffffffffu, s, 1);  s  += __shfl_xor_sync(0xffffffffu, s, 2);
    s2 += __shfl_xor_sync(0xffffffffu, s2, 1); s2 += __shfl_xor_sync(0xffffffffu, s2, 2);
    float mu = s * (1.f / 96.f);
    float rs = rsqrtf(s2 * (1.f / 96.f) - mu * mu + LN_EPS);
#pragma unroll
    for (int k = 0; k < 12; ++k) {
      int c = 24 * rq + 2 * k;
      float a = (v[2 * k] - mu) * rs * lnp[c] + lnp[96 + c];
      float b = (v[2 * k + 1] - mu) * rs * lnp[c + 1] + lnp[96 + c + 1];
      *(uint32_t*)(SM + OF_A + row * AST + 2 * c) = pkh(a, b);
    }
  };

  int w = blockIdx.x;
  if (w < NWIN) ln1(w);

  for (; w < NWIN; w += gridDim.x) {
    __syncthreads();  // A(w) ready; prior iteration fully drained

    // ---- QKV: hoisted A-fragments, each warp 48 cols of q,k,v ----
    {
      uint32_t af[6][4];
      const uint32_t aRow = sb + OF_A + (uint32_t)((m0 + (lane & 7) + ((lane >> 3) & 1) * 8) * AST + (lane >> 4) * 16);
#pragma unroll
      for (int s = 0; s < 6; ++s) ldm4(af[s], aRow + 32 * s);
#pragma unroll
      for (int c = 0; c < 3; ++c) {
        float d[6][4];
#pragma unroll
        for (int j = 0; j < 6; ++j) { d[j][0] = d[j][1] = d[j][2] = d[j][3] = 0.f; }
        const uint32_t wRow = prow(sb + OF_WQKV + (96 * c + 48 * g) * WST, WST, lane);
#pragma unroll
        for (int s = 0; s < 6; ++s)
#pragma unroll
          for (int jp = 0; jp < 3; ++jp) {
            uint32_t b[4];
            ldm4(b, wRow + (uint32_t)(16 * jp * WST) + 32 * s);
            mma16816(d[2 * jp], af[s], b);
            mma16816(d[2 * jp + 1], af[s], b + 2);
          }
        const int dst = (c == 0) ? OF_Q : (c == 1 ? OF_K : OF_V);
        const float sc = (c == 0) ? SCALE : 1.f;
#pragma unroll
        for (int j = 0; j < 6; ++j) {
          int col = 48 * g + 8 * j + 2 * qc;
          float b0 = bias[96 * c + col], b1 = bias[96 * c + col + 1];
          *(uint32_t*)(SM + dst + (m0 + qr) * AST + col * 2)     = pkh((d[j][0] + b0) * sc, (d[j][1] + b1) * sc);
          *(uint32_t*)(SM + dst + (m0 + qr + 8) * AST + col * 2) = pkh((d[j][2] + b0) * sc, (d[j][3] + b1) * sc);
        }
      }
    }
    __syncthreads();

    // ---- attention: g=0 -> heads 0,2 ; g=1 -> head 1 ----
    const int nn0 = m0 + qr, nn1 = nn0 + 8;
    for (int h = g; h < 3; h += 2) {
      float ds[8][4];
#pragma unroll
      for (int j = 0; j < 8; ++j) { ds[j][0] = ds[j][1] = ds[j][2] = ds[j][3] = 0.f; }
#pragma unroll
      for (int s = 0; s < 2; ++s) {
        uint32_t a[4];
        ldm4(a, sb + OF_Q + (uint32_t)((m0 + (lane & 7) + ((lane >> 3) & 1) * 8) * AST + (h * 32 + s * 16 + (lane >> 4) * 8) * 2));
        const uint32_t kRow = prow(sb + OF_K, AST, lane) + (uint32_t)((h * 32 + s * 16) * 2);
#pragma unroll
        for (int jp = 0; jp < 4; ++jp) {
          uint32_t b[4];
          ldm4(b, kRow + (uint32_t)(16 * jp * AST));
          mma16816(ds[2 * jp], a, b);
          mma16816(ds[2 * jp + 1], a, b + 2);
        }
      }
      float mx0 = -1e30f, mx1 = -1e30f;
#pragma unroll
      for (int j = 0; j < 8; ++j) {
        int mmc = 8 * j + 2 * qc;
        ds[j][0] += rpbs[RIDX[nn0 * 64 + mmc] * 3 + h];
        ds[j][1] += rpbs[RIDX[nn0 * 64 + mmc + 1] * 3 + h];
        ds[j][2] += rpbs[RIDX[nn1 * 64 + mmc] * 3 + h];
        ds[j][3] += rpbs[RIDX[nn1 * 64 + mmc + 1] * 3 + h];
        mx0 = fmaxf(mx0, fmaxf(ds[j][0], ds[j][1]));
        mx1 = fmaxf(mx1, fmaxf(ds[j][2], ds[j][3]));
      }
      mx0 = fmaxf(mx0, __shfl_xor_sync(0xffffffffu, mx0, 1));
      mx0 = fmaxf(mx0, __shfl_xor_sync(0xffffffffu, mx0, 2));
      mx1 = fmaxf(mx1, __shfl_xor_sync(0xffffffffu, mx1, 1));
      mx1 = fmaxf(mx1, __shfl_xor_sync(0xffffffffu, mx1, 2));
      float s0 = 0.f, s1 = 0.f;
#pragma unroll
      for (int j = 0; j < 8; ++j) {
        ds[j][0] = __expf(ds[j][0] - mx0); ds[j][1] = __expf(ds[j][1] - mx0);
        ds[j][2] = __expf(ds[j][2] - mx1); ds[j][3] = __expf(ds[j][3] - mx1);
        s0 += ds[j][0] + ds[j][1]; s1 += ds[j][2] + ds[j][3];
      }
      s0 += __shfl_xor_sync(0xffffffffu, s0, 1); s0 += __shfl_xor_sync(0xffffffffu, s0, 2);
      s1 += __shfl_xor_sync(0xffffffffu, s1, 1); s1 += __shfl_xor_sync(0xffffffffu, s1, 2);
      float i0 = 1.f / s0, i1 = 1.f / s1;
      uint32_t pa[4][4];
#pragma unroll
      for (int kk = 0; kk < 4; ++kk) {
        pa[kk][0] = pkh(ds[2 * kk][0] * i0, ds[2 * kk][1] * i0);
        pa[kk][1] = pkh(ds[2 * kk][2] * i1, ds[2 * kk][3] * i1);
        pa[kk][2] = pkh(ds[2 * kk + 1][0] * i0, ds[2 * kk + 1][1] * i0);
        pa[kk][3] = pkh(ds[2 * kk + 1][2] * i1, ds[2 * kk + 1][3] * i1);
      }
      float o[4][4];
#pragma unroll
      for (int j = 0; j < 4; ++j) { o[j][0] = o[j][1] = o[j][2] = o[j][3] = 0.f; }
#pragma unroll
      for (int kk = 0; kk < 4; ++kk) {
        const uint32_t vRow = sb + OF_V + (uint32_t)((16 * kk + (lane & 15)) * AST + (h * 32 + (lane >> 4) * 8) * 2);
#pragma unroll
        for (int jp = 0; jp < 2; ++jp) {
          uint32_t b[4];
          ldm4t(b, vRow + 32 * jp);
          mma16816(o[2 * jp], pa[kk], b);
          mma16816(o[2 * jp + 1], pa[kk], b + 2);
        }
      }
#pragma unroll
      for (int j = 0; j < 4; ++j) {
        int col = h * 32 + 8 * j + 2 * qc;
        *(uint32_t*)(SM + OF_A + (m0 + qr) * AST + col * 2)     = pkh(o[j][0], o[j][1]);
        *(uint32_t*)(SM + OF_A + (m0 + qr + 8) * AST + col * 2) = pkh(o[j][2], o[j][3]);
      }
    }
    __syncthreads();

    // ---- proj -> Q (f16) ----
    {
      float d[6][4];
      wgemm<6, 6>(sb + OF_A, AST, sb + OF_WPRJ + 48 * g * WST, WST, m0, lane, d);
#pragma unroll
      for (int j = 0; j < 6; ++j) {
        int col = 48 * g + 8 * j + 2 * qc;
        float b0 = bias[288 + col], b1 = bias[288 + col + 1];
        *(uint32_t*)(SM + OF_Q + (m0 + qr) * AST + col * 2)     = pkh(d[j][0] + b0, d[j][1] + b1);
        *(uint32_t*)(SM + OF_Q + (m0 + qr + 8) * AST + col * 2) = pkh(d[j][2] + b0, d[j][3] + b1);
      }
    }
    __syncthreads();

    // ---- LN2: Q -> A (f16) ----
    {
      const __half2* qrow = (const __half2*)(SM + OF_Q + row * AST);
      float v[24], s = 0.f, s2 = 0.f;
#pragma unroll
      for (int k = 0; k < 12; ++k) {
        float2 u = __half22float2(qrow[12 * rq + k]);
        v[2 * k] = u.x; v[2 * k + 1] = u.y;
        s += u.x + u.y; s2 += u.x * u.x + u.y * u.y;
      }
      s  += __shfl_xor_sync(0xffffffffu, s, 1);  s  += __shfl_xor_sync(0xffffffffu, s, 2);
      s2 += __shfl_xor_sync(0xffffffffu, s2, 1); s2 += __shfl_xor_sync(0xffffffffu, s2, 2);
      float mu = s * (1.f / 96.f);
      float rs = rsqrtf(s2 * (1.f / 96.f) - mu * mu + LN_EPS);
#pragma unroll
      for (int k = 0; k < 12; ++k) {
        int c = 24 * rq + 2 * k;
        float a = (v[2 * k] - mu) * rs * lnp[192 + c] + lnp[288 + c];
        float b = (v[2 * k + 1] - mu) * rs * lnp[192 + c + 1] + lnp[288 + c + 1];
        *(uint32_t*)(SM + OF_A + row * AST + 2 * c) = pkh(a, b);
      }
    }
    __syncthreads();

    // ---- fc1 + exact GELU -> hid ----
    {
      float d[12][4];
      wgemm<12, 6>(sb + OF_A, AST, sb + OF_WFC1 + 96 * g * WST, WST, m0, lane, d);
#pragma unroll
      for (int j = 0; j < 12; ++j) {
        int col = 96 * g + 8 * j + 2 * qc;
        float b0 = bias[384 + col], b1 = bias[384 + col + 1];
        float u0 = d[j][0] + b0, u1 = d[j][1] + b1, u2 = d[j][2] + b0, u3 = d[j][3] + b1;
        u0 = 0.5f * u0 * (1.f + erff(u0 * 0.70710678118654752f));
        u1 = 0.5f * u1 * (1.f + erff(u1 * 0.70710678118654752f));
        u2 = 0.5f * u2 * (1.f + erff(u2 * 0.70710678118654752f));
        u3 = 0.5f * u3 * (1.f + erff(u3 * 0.70710678118654752f));
        *(uint32_t*)(SM + OF_HID + (m0 + qr) * HST + col * 2)     = pkh(u0, u1);
        *(uint32_t*)(SM + OF_HID + (m0 + qr + 8) * HST + col * 2) = pkh(u2, u3);
      }
    }
    __syncthreads();

    // ---- fc2 -> gmem fused residual ; prefetch LN1(next) ----
    {
      float d[6][4];
      wgemm<6, 12>(sb + OF_HID, HST, sb + OF_WFC2 + 48 * g * HST, HST, m0, lane, d);
      const int wb = w >> 10, wh = (w >> 5) & 31, ww = w & 31;
      const size_t base = ((size_t)wb * 96) * 65536 + (size_t)(wh * 8) * 256 + ww * 8;
      const int sp0 = (m0 >> 3) * 256 + qr, sp1 = sp0 + 256;
#pragma unroll
      for (int j = 0; j < 6; ++j) {
        int col = 48 * g + 8 * j + 2 * qc;
        float b0 = bias[576 + col], b1 = bias[576 + col + 1];
        size_t o00 = base + (size_t)col * 65536 + sp0;
        size_t o10 = base + (size_t)col * 65536 + sp1;
        out[o00]         = d[j][0] + b0 + x[o00];
        out[o00 + 65536] = d[j][1] + b1 + x[o00 + 65536];
        out[o10]         = d[j][2] + b0 + x[o10];
        out[o10 + 65536] = d[j][3] + b1 + x[o10 + 65536];
      }
    }
    int wn = w + gridDim.x;
    if (wn < NWIN) ln1(wn);
  }
}

extern "C" void kernel_launch(void* const* d_in, const int* in_sizes, int n_in,
                              void* d_out, int out_size) {
  (void)in_sizes; (void)n_in; (void)out_size;
  int dev = 0, sms = 148;
  cudaGetDevice(&dev);
  cudaDeviceGetAttribute(&sms, cudaDevAttrMultiProcessorCount, dev);
  cudaFuncSetAttribute(swin_kernel, cudaFuncAttributeMaxDynamicSharedMemorySize, SMEM_TOTAL);
  swin_kernel<<<sms, THREADS, SMEM_TOTAL>>>(
      (const float*)d_in[0],
      (const float*)d_in[1], (const float*)d_in[2],
      (const float*)d_in[3], (const float*)d_in[4],
      (const float*)d_in[5],
      (const float*)d_in[6], (const float*)d_in[7],
      (const float*)d_in[8], (const float*)d_in[9],
      (const float*)d_in[10], (const float*)d_in[11],
      (const float*)d_in[12], (const float*)d_in[13],
      (float*)d_out);
}